// round 1
// baseline (speedup 1.0000x reference)
#include <cuda_runtime.h>
#include <cuda_bf16.h>

#define N_NODES 50000
#define HF 128          // H*F
#define H_HEADS 4
#define F_FEAT 32
#define NODES_PER_BLK 32

// ---------------- scratch (static device globals; no allocation) ----------------
__device__ float    g_z[N_NODES * HF];     // z of current layer
__device__ float    g_acc1[N_NODES * HF];  // layer-1 accumulator (pre-ELU h1)
__device__ float    g_acc2[N_NODES * HF];  // layer-2 accumulator
__device__ float    g_el[N_NODES * H_HEADS];
__device__ float    g_er[N_NODES * H_HEADS];
__device__ float    g_s [N_NODES * H_HEADS];
__device__ unsigned g_m [N_NODES * H_HEADS];  // ordered-uint max

// ---------------- float <-> order-preserving uint ----------------
__device__ __forceinline__ unsigned f2o(float f) {
    unsigned u = __float_as_uint(f);
    return (u & 0x80000000u) ? ~u : (u | 0x80000000u);
}
__device__ __forceinline__ float o2f(unsigned u) {
    return __uint_as_float((u & 0x80000000u) ? (u & 0x7fffffffu) : ~u);
}

__device__ __forceinline__ float leaky(float v) { return v > 0.f ? v : 0.2f * v; }
__device__ __forceinline__ float elu(float v)   { return v > 0.f ? v : (expf(v) - 1.f); }

// ---------------- K1: z = act(x) @ W ; el/er ; init acc/m/s ----------------
// block = 128 threads (thread j = output column), 32 nodes per block.
__global__ __launch_bounds__(128)
void gemm_attn_kernel(const float* __restrict__ x,
                      const float* __restrict__ W,
                      const float* __restrict__ al,
                      const float* __restrict__ ar,
                      const float* __restrict__ bias,
                      int apply_elu_on_input,
                      float* __restrict__ z,
                      float* __restrict__ acc,
                      float* __restrict__ el,
                      float* __restrict__ er,
                      unsigned* __restrict__ m_ord,
                      float* __restrict__ s)
{
    __shared__ float xs[NODES_PER_BLK * HF];  // 16 KB
    const int j  = threadIdx.x;               // 0..127
    const int n0 = blockIdx.x * NODES_PER_BLK;

    // load (and optionally ELU) the 32 input rows
    #pragma unroll
    for (int nn = 0; nn < NODES_PER_BLK; nn++) {
        int n = n0 + nn;
        float xv = 0.f;
        if (n < N_NODES) xv = x[n * HF + j];
        if (apply_elu_on_input) xv = elu(xv);
        xs[nn * HF + j] = xv;
    }
    __syncthreads();

    float sum[NODES_PER_BLK];
    #pragma unroll
    for (int nn = 0; nn < NODES_PER_BLK; nn++) sum[nn] = 0.f;

    // register-blocked GEMM: 4 W values per step, float4 LDS of x
    for (int k = 0; k < HF; k += 4) {
        float w0 = W[(k + 0) * HF + j];
        float w1 = W[(k + 1) * HF + j];
        float w2 = W[(k + 2) * HF + j];
        float w3 = W[(k + 3) * HF + j];
        #pragma unroll
        for (int nn = 0; nn < NODES_PER_BLK; nn++) {
            float4 xv = *reinterpret_cast<const float4*>(&xs[nn * HF + k]);
            sum[nn] += xv.x * w0 + xv.y * w1 + xv.z * w2 + xv.w * w3;
        }
    }

    const float alj = al[j], arj = ar[j], bj = bias[j];
    const int h = j >> 5, f = j & 31;

    #pragma unroll
    for (int nn = 0; nn < NODES_PER_BLK; nn++) {
        int n = n0 + nn;
        if (n >= N_NODES) break;
        z[n * HF + j]   = sum[nn];
        acc[n * HF + j] = xs[nn * HF + j] + bj;   // residual + bias (act already applied)
        float pl = sum[nn] * alj;
        float pr = sum[nn] * arj;
        #pragma unroll
        for (int off = 16; off; off >>= 1) {
            pl += __shfl_down_sync(0xffffffffu, pl, off);
            pr += __shfl_down_sync(0xffffffffu, pr, off);
        }
        if (f == 0) {
            el[n * H_HEADS + h] = pl;
            er[n * H_HEADS + h] = pr;
            m_ord[n * H_HEADS + h] = 0u;   // below every real ordered value
            s[n * H_HEADS + h]  = 0.f;
        }
    }
}

// ---------------- K2: segment max over dst ----------------
__global__ __launch_bounds__(256)
void edge_max_kernel(const int* __restrict__ src, const int* __restrict__ dst, int E,
                     const float* __restrict__ el, const float* __restrict__ er,
                     unsigned* __restrict__ m_ord)
{
    int i = blockIdx.x * blockDim.x + threadIdx.x;
    if (i >= E * H_HEADS) return;
    int e = i >> 2, h = i & 3;
    int sn = src[e], dn = dst[e];
    float v = leaky(el[sn * H_HEADS + h] + er[dn * H_HEADS + h]);
    atomicMax(&m_ord[dn * H_HEADS + h], f2o(v));
}

// ---------------- K3: segment sum of exp ----------------
__global__ __launch_bounds__(256)
void edge_sum_kernel(const int* __restrict__ src, const int* __restrict__ dst, int E,
                     const float* __restrict__ el, const float* __restrict__ er,
                     const unsigned* __restrict__ m_ord, float* __restrict__ s)
{
    int i = blockIdx.x * blockDim.x + threadIdx.x;
    if (i >= E * H_HEADS) return;
    int e = i >> 2, h = i & 3;
    int sn = src[e], dn = dst[e];
    float v = leaky(el[sn * H_HEADS + h] + er[dn * H_HEADS + h]);
    float ex = expf(v - o2f(m_ord[dn * H_HEADS + h]));
    atomicAdd(&s[dn * H_HEADS + h], ex);
}

// ---------------- K4: weighted scatter (one warp per edge, float4 red) ----------------
__global__ __launch_bounds__(256)
void edge_scatter_kernel(const int* __restrict__ src, const int* __restrict__ dst, int E,
                         const float* __restrict__ el, const float* __restrict__ er,
                         const unsigned* __restrict__ m_ord, const float* __restrict__ s,
                         const float* __restrict__ z, float* __restrict__ acc)
{
    int gid  = blockIdx.x * blockDim.x + threadIdx.x;
    int e    = gid >> 5;
    int lane = threadIdx.x & 31;
    if (e >= E) return;

    int sn = src[e], dn = dst[e];

    float av = 0.f;
    if (lane < H_HEADS) {
        float v = leaky(el[sn * H_HEADS + lane] + er[dn * H_HEADS + lane]);
        float m = o2f(m_ord[dn * H_HEADS + lane]);
        av = expf(v - m) / fmaxf(s[dn * H_HEADS + lane], 1e-9f);
    }
    int h   = lane >> 3;                       // 4 consecutive floats per lane -> head
    float a = __shfl_sync(0xffffffffu, av, h);

    float4 zv = *reinterpret_cast<const float4*>(&z[sn * HF + lane * 4]);
    float4 mv = make_float4(zv.x * a, zv.y * a, zv.z * a, zv.w * a);
    atomicAdd(reinterpret_cast<float4*>(&acc[dn * HF + lane * 4]), mv);
}

// ---------------- K5: mean over heads + projection ----------------
__global__ __launch_bounds__(256)
void finalize_kernel(const float* __restrict__ acc,
                     const float* __restrict__ Wp, const float* __restrict__ bp,
                     float* __restrict__ out)
{
    int gid  = blockIdx.x * blockDim.x + threadIdx.x;
    int n    = gid >> 5;
    int lane = threadIdx.x & 31;
    if (n >= N_NODES) return;
    float t = 0.25f * (acc[n * HF + lane]      + acc[n * HF + 32 + lane] +
                       acc[n * HF + 64 + lane] + acc[n * HF + 96 + lane]);
    float v = t * Wp[lane];
    #pragma unroll
    for (int off = 16; off; off >>= 1) v += __shfl_down_sync(0xffffffffu, v, off);
    if (lane == 0) out[n] = v + bp[0];
}

// ---------------- launch ----------------
extern "C" void kernel_launch(void* const* d_in, const int* in_sizes, int n_in,
                              void* d_out, int out_size)
{
    const float* feats = (const float*)d_in[0];
    const int*   src   = (const int*)  d_in[1];
    const int*   dst   = (const int*)  d_in[2];
    const float* W1    = (const float*)d_in[3];
    const float* al1   = (const float*)d_in[4];
    const float* ar1   = (const float*)d_in[5];
    const float* b1    = (const float*)d_in[6];
    const float* W2    = (const float*)d_in[7];
    const float* al2   = (const float*)d_in[8];
    const float* ar2   = (const float*)d_in[9];
    const float* b2    = (const float*)d_in[10];
    const float* Wp    = (const float*)d_in[11];
    const float* bp    = (const float*)d_in[12];
    float* out = (float*)d_out;

    const int E = in_sizes[1];

    float *z, *acc1, *acc2, *el, *er, *s; unsigned* m;
    cudaGetSymbolAddress((void**)&z,    g_z);
    cudaGetSymbolAddress((void**)&acc1, g_acc1);
    cudaGetSymbolAddress((void**)&acc2, g_acc2);
    cudaGetSymbolAddress((void**)&el,   g_el);
    cudaGetSymbolAddress((void**)&er,   g_er);
    cudaGetSymbolAddress((void**)&s,    g_s);
    cudaGetSymbolAddress((void**)&m,    g_m);

    const int gemm_grid = (N_NODES + NODES_PER_BLK - 1) / NODES_PER_BLK;
    const int eh_grid   = (E * H_HEADS + 255) / 256;
    const int ew_grid   = (E * 32 + 255) / 256;       // one warp per edge
    const int fin_grid  = (N_NODES * 32 + 255) / 256; // one warp per node

    // ---- layer 1 ----
    gemm_attn_kernel<<<gemm_grid, 128>>>(feats, W1, al1, ar1, b1, 0,
                                         z, acc1, el, er, m, s);
    edge_max_kernel    <<<eh_grid, 256>>>(src, dst, E, el, er, m);
    edge_sum_kernel    <<<eh_grid, 256>>>(src, dst, E, el, er, m, s);
    edge_scatter_kernel<<<ew_grid, 256>>>(src, dst, E, el, er, m, s, z, acc1);

    // ---- layer 2 (ELU applied on input read; residual uses ELU'd h1) ----
    gemm_attn_kernel<<<gemm_grid, 128>>>(acc1, W2, al2, ar2, b2, 1,
                                         z, acc2, el, er, m, s);
    edge_max_kernel    <<<eh_grid, 256>>>(src, dst, E, el, er, m);
    edge_sum_kernel    <<<eh_grid, 256>>>(src, dst, E, el, er, m, s);
    edge_scatter_kernel<<<ew_grid, 256>>>(src, dst, E, el, er, m, s, z, acc2);

    // ---- head: mean over heads + projection ----
    finalize_kernel<<<fin_grid, 256>>>(acc2, Wp, bp, out);
}

// round 2
// speedup vs baseline: 1.4263x; 1.4263x over previous
#include <cuda_runtime.h>
#include <cuda_bf16.h>

#define N_NODES 50000
#define HF 128          // H*F
#define H_HEADS 4
#define NODES_PER_BLK 32
#define E_MAX 1000000
#define DEG_CAP 128     // smem cache capacity per node (avg deg ~16)
#define SCAN_BLK 1024
#define N_SCAN_BLKS ((N_NODES + SCAN_BLK - 1) / SCAN_BLK)

// ---------------- scratch (static device globals; no allocation) ----------------
__device__ float g_z[N_NODES * HF];
__device__ float g_acc1[N_NODES * HF];
__device__ float g_acc2[N_NODES * HF];
__device__ float g_el[N_NODES * H_HEADS];
__device__ float g_er[N_NODES * H_HEADS];
__device__ int   g_deg[N_NODES];
__device__ int   g_rowptr[N_NODES];
__device__ int   g_cursor[N_NODES];
__device__ int   g_incl[N_NODES];
__device__ int   g_bsum[N_SCAN_BLKS];
__device__ int   g_boff[N_SCAN_BLKS];
__device__ int   g_csr_src[E_MAX];

__device__ __forceinline__ float leaky(float v) { return v > 0.f ? v : 0.2f * v; }
__device__ __forceinline__ float elu(float v)   { return v > 0.f ? v : (__expf(v) - 1.f); }

// ---------------- CSR build ----------------
__global__ void zero_deg_kernel(int* deg) {
    int i = blockIdx.x * blockDim.x + threadIdx.x;
    if (i < N_NODES) deg[i] = 0;
}

__global__ void hist_kernel(const int* __restrict__ dst, int E, int* __restrict__ deg) {
    int i = blockIdx.x * blockDim.x + threadIdx.x;
    if (i < E) atomicAdd(&deg[dst[i]], 1);
}

__global__ __launch_bounds__(SCAN_BLK)
void scan1_kernel(const int* __restrict__ deg, int* __restrict__ incl, int* __restrict__ bsum) {
    __shared__ int sm[SCAN_BLK];
    int tid = threadIdx.x;
    int i = blockIdx.x * SCAN_BLK + tid;
    int v = (i < N_NODES) ? deg[i] : 0;
    sm[tid] = v;
    __syncthreads();
    #pragma unroll
    for (int off = 1; off < SCAN_BLK; off <<= 1) {
        int t = (tid >= off) ? sm[tid - off] : 0;
        __syncthreads();
        sm[tid] += t;
        __syncthreads();
    }
    if (i < N_NODES) incl[i] = sm[tid];
    if (tid == SCAN_BLK - 1) bsum[blockIdx.x] = sm[tid];
}

__global__ void scan2_kernel(const int* __restrict__ bsum, int* __restrict__ boff) {
    __shared__ int sm[64];
    int tid = threadIdx.x;   // blockDim = 64 >= N_SCAN_BLKS
    sm[tid] = (tid < N_SCAN_BLKS) ? bsum[tid] : 0;
    __syncthreads();
    #pragma unroll
    for (int off = 1; off < 64; off <<= 1) {
        int t = (tid >= off) ? sm[tid - off] : 0;
        __syncthreads();
        sm[tid] += t;
        __syncthreads();
    }
    if (tid < N_SCAN_BLKS) boff[tid] = sm[tid] - bsum[tid];  // exclusive
}

__global__ void scan3_kernel(const int* __restrict__ incl, const int* __restrict__ deg,
                             const int* __restrict__ boff,
                             int* __restrict__ rowptr, int* __restrict__ cursor) {
    int i = blockIdx.x * blockDim.x + threadIdx.x;
    if (i >= N_NODES) return;
    int excl = incl[i] - deg[i] + boff[i / SCAN_BLK];
    rowptr[i] = excl;
    cursor[i] = excl;
}

__global__ void fill_kernel(const int* __restrict__ src, const int* __restrict__ dst, int E,
                            int* __restrict__ cursor, int* __restrict__ csr_src) {
    int i = blockIdx.x * blockDim.x + threadIdx.x;
    if (i >= E) return;
    int pos = atomicAdd(&cursor[dst[i]], 1);
    csr_src[pos] = src[i];
}

// ---------------- K1: z = act(x) @ W ; el/er ; base = residual + bias ----------------
__global__ __launch_bounds__(128)
void gemm_attn_kernel(const float* __restrict__ x,
                      const float* __restrict__ W,
                      const float* __restrict__ al,
                      const float* __restrict__ ar,
                      const float* __restrict__ bias,
                      int apply_elu_on_input,
                      float* __restrict__ z,
                      float* __restrict__ base,
                      float* __restrict__ el,
                      float* __restrict__ er)
{
    __shared__ float xs[NODES_PER_BLK * HF];  // 16 KB
    const int j  = threadIdx.x;               // 0..127
    const int n0 = blockIdx.x * NODES_PER_BLK;

    #pragma unroll
    for (int nn = 0; nn < NODES_PER_BLK; nn++) {
        int n = n0 + nn;
        float xv = 0.f;
        if (n < N_NODES) xv = x[n * HF + j];
        if (apply_elu_on_input) xv = elu(xv);
        xs[nn * HF + j] = xv;
    }
    __syncthreads();

    float sum[NODES_PER_BLK];
    #pragma unroll
    for (int nn = 0; nn < NODES_PER_BLK; nn++) sum[nn] = 0.f;

    for (int k = 0; k < HF; k += 4) {
        float w0 = W[(k + 0) * HF + j];
        float w1 = W[(k + 1) * HF + j];
        float w2 = W[(k + 2) * HF + j];
        float w3 = W[(k + 3) * HF + j];
        #pragma unroll
        for (int nn = 0; nn < NODES_PER_BLK; nn++) {
            float4 xv = *reinterpret_cast<const float4*>(&xs[nn * HF + k]);
            sum[nn] += xv.x * w0 + xv.y * w1 + xv.z * w2 + xv.w * w3;
        }
    }

    const float alj = al[j], arj = ar[j], bj = bias[j];
    const int h = j >> 5, f = j & 31;

    #pragma unroll
    for (int nn = 0; nn < NODES_PER_BLK; nn++) {
        int n = n0 + nn;
        if (n >= N_NODES) break;
        z[n * HF + j]    = sum[nn];
        base[n * HF + j] = xs[nn * HF + j] + bj;
        float pl = sum[nn] * alj;
        float pr = sum[nn] * arj;
        #pragma unroll
        for (int off = 16; off; off >>= 1) {
            pl += __shfl_down_sync(0xffffffffu, pl, off);
            pr += __shfl_down_sync(0xffffffffu, pr, off);
        }
        if (f == 0) {
            el[n * H_HEADS + h] = pl;
            er[n * H_HEADS + h] = pr;
        }
    }
}

// ---------------- fused per-node softmax + aggregate (one warp per node, no atomics) ----
__global__ __launch_bounds__(256)
void gat_aggregate_kernel(const int* __restrict__ rowptr, const int* __restrict__ deg,
                          const int* __restrict__ csr_src,
                          const float* __restrict__ el, const float* __restrict__ er,
                          const float* __restrict__ z, float* __restrict__ hout)
{
    __shared__ int    s_src[8][DEG_CAP];
    __shared__ float4 s_att[8][DEG_CAP];

    const int wid  = threadIdx.x >> 5;
    const int lane = threadIdx.x & 31;
    const int n    = blockIdx.x * 8 + wid;
    if (n >= N_NODES) return;

    const int beg = rowptr[n];
    const int d   = deg[n];

    const float4 er4 = *reinterpret_cast<const float4*>(er + n * H_HEADS);

    // pass 1: exp numerators + denominator (warp-strided over in-edges)
    float s0 = 0.f, s1 = 0.f, s2 = 0.f, s3 = 0.f;
    for (int i = lane; i < d; i += 32) {
        int sn = __ldg(&csr_src[beg + i]);
        float4 el4 = *reinterpret_cast<const float4*>(el + sn * H_HEADS);
        float e0 = __expf(leaky(el4.x + er4.x));
        float e1 = __expf(leaky(el4.y + er4.y));
        float e2 = __expf(leaky(el4.z + er4.z));
        float e3 = __expf(leaky(el4.w + er4.w));
        s0 += e0; s1 += e1; s2 += e2; s3 += e3;
        if (i < DEG_CAP) {
            s_src[wid][i] = sn;
            s_att[wid][i] = make_float4(e0, e1, e2, e3);
        }
    }
    #pragma unroll
    for (int off = 16; off; off >>= 1) {
        s0 += __shfl_xor_sync(0xffffffffu, s0, off);
        s1 += __shfl_xor_sync(0xffffffffu, s1, off);
        s2 += __shfl_xor_sync(0xffffffffu, s2, off);
        s3 += __shfl_xor_sync(0xffffffffu, s3, off);
    }

    const int h = lane >> 3;                 // head of this lane's feature chunk
    float sh  = (h == 0) ? s0 : (h == 1) ? s1 : (h == 2) ? s2 : s3;
    float sinv = 1.f / fmaxf(sh, 1e-9f);
    float erh  = (h == 0) ? er4.x : (h == 1) ? er4.y : (h == 2) ? er4.z : er4.w;

    // pass 2: accumulate attn * z[src] in registers; init from residual+bias base
    float4 acc = *reinterpret_cast<const float4*>(hout + n * HF + lane * 4);
    __syncwarp();

    for (int i = 0; i < d; ++i) {
        int sn; float ev;
        if (i < DEG_CAP) {
            sn = s_src[wid][i];
            float4 a4 = s_att[wid][i];
            ev = (h == 0) ? a4.x : (h == 1) ? a4.y : (h == 2) ? a4.z : a4.w;
        } else {
            sn = __ldg(&csr_src[beg + i]);
            ev = __expf(leaky(__ldg(&el[sn * H_HEADS + h]) + erh));
        }
        float a = ev * sinv;
        float4 zv = *reinterpret_cast<const float4*>(z + sn * HF + lane * 4);
        acc.x += a * zv.x;
        acc.y += a * zv.y;
        acc.z += a * zv.z;
        acc.w += a * zv.w;
    }
    *reinterpret_cast<float4*>(hout + n * HF + lane * 4) = acc;
}

// ---------------- K5: mean over heads + projection ----------------
__global__ __launch_bounds__(256)
void finalize_kernel(const float* __restrict__ acc,
                     const float* __restrict__ Wp, const float* __restrict__ bp,
                     float* __restrict__ out)
{
    int gid  = blockIdx.x * blockDim.x + threadIdx.x;
    int n    = gid >> 5;
    int lane = threadIdx.x & 31;
    if (n >= N_NODES) return;
    float t = 0.25f * (acc[n * HF + lane]      + acc[n * HF + 32 + lane] +
                       acc[n * HF + 64 + lane] + acc[n * HF + 96 + lane]);
    float v = t * Wp[lane];
    #pragma unroll
    for (int off = 16; off; off >>= 1) v += __shfl_down_sync(0xffffffffu, v, off);
    if (lane == 0) out[n] = v + bp[0];
}

// ---------------- launch ----------------
extern "C" void kernel_launch(void* const* d_in, const int* in_sizes, int n_in,
                              void* d_out, int out_size)
{
    const float* feats = (const float*)d_in[0];
    const int*   src   = (const int*)  d_in[1];
    const int*   dst   = (const int*)  d_in[2];
    const float* W1    = (const float*)d_in[3];
    const float* al1   = (const float*)d_in[4];
    const float* ar1   = (const float*)d_in[5];
    const float* b1    = (const float*)d_in[6];
    const float* W2    = (const float*)d_in[7];
    const float* al2   = (const float*)d_in[8];
    const float* ar2   = (const float*)d_in[9];
    const float* b2    = (const float*)d_in[10];
    const float* Wp    = (const float*)d_in[11];
    const float* bp    = (const float*)d_in[12];
    float* out = (float*)d_out;

    const int E = in_sizes[1];

    float *z, *acc1, *acc2, *el, *er;
    int *deg, *rowptr, *cursor, *incl, *bsum, *boff, *csr_src;
    cudaGetSymbolAddress((void**)&z,       g_z);
    cudaGetSymbolAddress((void**)&acc1,    g_acc1);
    cudaGetSymbolAddress((void**)&acc2,    g_acc2);
    cudaGetSymbolAddress((void**)&el,      g_el);
    cudaGetSymbolAddress((void**)&er,      g_er);
    cudaGetSymbolAddress((void**)&deg,     g_deg);
    cudaGetSymbolAddress((void**)&rowptr,  g_rowptr);
    cudaGetSymbolAddress((void**)&cursor,  g_cursor);
    cudaGetSymbolAddress((void**)&incl,    g_incl);
    cudaGetSymbolAddress((void**)&bsum,    g_bsum);
    cudaGetSymbolAddress((void**)&boff,    g_boff);
    cudaGetSymbolAddress((void**)&csr_src, g_csr_src);

    const int node_grid = (N_NODES + 255) / 256;
    const int edge_grid = (E + 255) / 256;
    const int gemm_grid = (N_NODES + NODES_PER_BLK - 1) / NODES_PER_BLK;
    const int agg_grid  = (N_NODES + 7) / 8;          // 8 warps (nodes) per block
    const int fin_grid  = (N_NODES * 32 + 255) / 256;

    // ---- CSR build (by dst) ----
    zero_deg_kernel<<<node_grid, 256>>>(deg);
    hist_kernel   <<<edge_grid, 256>>>(dst, E, deg);
    scan1_kernel  <<<N_SCAN_BLKS, SCAN_BLK>>>(deg, incl, bsum);
    scan2_kernel  <<<1, 64>>>(bsum, boff);
    scan3_kernel  <<<node_grid, 256>>>(incl, deg, boff, rowptr, cursor);
    fill_kernel   <<<edge_grid, 256>>>(src, dst, E, cursor, csr_src);

    // ---- layer 1 ----
    gemm_attn_kernel   <<<gemm_grid, 128>>>(feats, W1, al1, ar1, b1, 0, z, acc1, el, er);
    gat_aggregate_kernel<<<agg_grid, 256>>>(rowptr, deg, csr_src, el, er, z, acc1);

    // ---- layer 2 (ELU applied on input read; residual uses ELU'd h1) ----
    gemm_attn_kernel   <<<gemm_grid, 128>>>(acc1, W2, al2, ar2, b2, 1, z, acc2, el, er);
    gat_aggregate_kernel<<<agg_grid, 256>>>(rowptr, deg, csr_src, el, er, z, acc2);

    // ---- head: mean over heads + projection ----
    finalize_kernel<<<fin_grid, 256>>>(acc2, Wp, bp, out);
}